// round 7
// baseline (speedup 1.0000x reference)
#include <cuda_runtime.h>
#include <math.h>

// P2V: out[b,vox] = top2-margin of softmax_n( |s2| * exp(-|s1| * |xyz[b,:,n]-grid[:,vox]|^2) )
// margin = (exp(v0)-exp(v1)) / sum_n exp(v_n),  v_n in (0,1]
//
// v_n = 2^( kx0*g0 + kx1*g1 + kx2*g2 + p_n + lw_vox )   (one MUFU ex2 per n)
// Pair-packed per-(b,n) tables staged in SHARED MEMORY per block (deterministic LDS):
//   sT[0][bb][pair] = {kx0_n,kx0_n1, kx1_n,kx1_n1}
//   sT[1][bb][pair] = {kx2_n,kx2_n1, p_n,  p_n1 }
// Sum of exp(v): deg-4 minimax poly, S=fma2(Q,v,S), +1024*c0 once.
// Top-2 tracked on the exponent acc (monotone) via scalar FMNMX (ALU pipe).

typedef unsigned long long u64;

#define VOXN 32768
#define NN   1024

__device__ __align__(256) float4 TABg[2][4][512];   // [half][batch][pair]
__device__ __align__(16)  float4 g_vox[VOXN];

__device__ __forceinline__ u64 pk2(float lo, float hi) {
    u64 r; asm("mov.b64 %0, {%1, %2};" : "=l"(r) : "f"(lo), "f"(hi)); return r;
}
__device__ __forceinline__ void upk2(u64 v, float& lo, float& hi) {
    asm("mov.b64 {%0, %1}, %2;" : "=f"(lo), "=f"(hi) : "l"(v));
}
__device__ __forceinline__ u64 fma2(u64 a, u64 b, u64 c) {
    u64 d; asm("fma.rn.f32x2 %0, %1, %2, %3;" : "=l"(d) : "l"(a), "l"(b), "l"(c)); return d;
}
__device__ __forceinline__ u64 add2(u64 a, u64 b) {
    u64 d; asm("add.rn.f32x2 %0, %1, %2;" : "=l"(d) : "l"(a), "l"(b)); return d;
}
__device__ __forceinline__ float ex2f(float x) {
    float r; asm("ex2.approx.ftz.f32 %0, %1;" : "=f"(r) : "f"(x)); return r;
}

// deg-4 minimax for e^x on [0,1], |err| ~ 3e-5
#define C4F 0.0695600f
#define C3F 0.1400096f
#define C2F 0.5099252f
#define C1F 0.9987378f
#define C0F 1.0000236f

// ---- fused prologue: blocks 0-127 per-voxel, blocks 128-143 per-(b,n) tables ----
__global__ void pv_prep(const float* __restrict__ xyz,
                        const float* __restrict__ grid,
                        const float* __restrict__ s1,
                        const float* __restrict__ s2) {
    const float L = 1.4426950408889634f;
    float s1a = fabsf(s1[0]);
    if (blockIdx.x < 128) {
        int vx = blockIdx.x * 256 + threadIdx.x;
        float g0 = grid[vx];
        float g1 = grid[VOXN + vx];
        float g2 = grid[2 * VOXN + vx];
        float lw = __log2f(fabsf(s2[0])) - s1a * L * (g0 * g0 + g1 * g1 + g2 * g2);
        g_vox[vx] = make_float4(g0, g1, g2, lw);
    } else {
        int i = (blockIdx.x - 128) * 256 + threadIdx.x;   // 0..4095
        if (i >= 4 * NN) return;
        int b = i >> 10, n = i & (NN - 1);
        float k = 2.0f * s1a * L;
        float x0 = xyz[b * 3 * NN + 0 * NN + n];
        float x1 = xyz[b * 3 * NN + 1 * NN + n];
        float x2 = xyz[b * 3 * NN + 2 * NN + n];
        int pr = n >> 1, h = n & 1;
        float* t01 = reinterpret_cast<float*>(&TABg[0][b][pr]);
        float* t23 = reinterpret_cast<float*>(&TABg[1][b][pr]);
        t01[0 + h] = k * x0;
        t01[2 + h] = k * x1;
        t23[0 + h] = k * x2;
        t23[2 + h] = -s1a * L * (x0 * x0 + x1 * x1 + x2 * x2);
    }
}

// ---- main: one warp -> 4 voxels x 2 batches = 8 outputs --------------------
// block = 8 warps, one batch-pair, 32 consecutive voxels; tables staged in smem.
__global__ void __launch_bounds__(256, 3) pv_main(float* __restrict__ out)
{
    __shared__ __align__(16) float4 sT[2][2][512];   // 32 KB: [half][batch-in-pair][pair]

    int tid  = threadIdx.x;
    int lane = tid & 31;
    int wig  = tid >> 5;                 // 0..7
    int bh   = blockIdx.x & 1;           // batches {2bh, 2bh+1}
    int vsg  = blockIdx.x >> 1;          // 0..1023
    int vox0 = vsg * 32 + wig * 4;

    // cooperative staging: 2048 float4 by 256 threads
    #pragma unroll
    for (int i = 0; i < 8; i++) {
        int idx  = tid + i * 256;
        int half = idx >> 10, bb = (idx >> 9) & 1, pr = idx & 511;
        sT[half][bb][pr] = TABg[half][2 * bh + bb][pr];
    }
    __syncthreads();

    // per-voxel broadcast constants
    u64 G[4][3], LW[4];
    #pragma unroll
    for (int v = 0; v < 4; v++) {
        float4 gv = g_vox[vox0 + v];
        G[v][0] = pk2(gv.x, gv.x);
        G[v][1] = pk2(gv.y, gv.y);
        G[v][2] = pk2(gv.z, gv.z);
        LW[v]   = pk2(gv.w, gv.w);
    }

    const u64 Cq3 = pk2(C4F, C4F);
    const u64 Cq2 = pk2(C3F, C3F);
    const u64 Cq1 = pk2(C2F, C2F);
    const u64 Cq0 = pk2(C1F, C1F);

    u64 S[8];
    float m0[8], m1[8];
    #pragma unroll
    for (int o = 0; o < 8; o++) { S[o] = 0ull; m0[o] = -1e30f; m1[o] = -1e30f; }

    // smem base for this lane; the 4 loads per iteration are fixed offsets off it
    const char* sbase = reinterpret_cast<const char*>(&sT[0][0][lane]);
    const int OFFB  = 512 * 16;           // next batch within a half (8 KB)
    const int OFF23 = 2 * 512 * 16;       // half 1 (16 KB)

    #pragma unroll 1
    for (int j = 0; j < 16; j++) {
        ulonglong2 a01 = *reinterpret_cast<const ulonglong2*>(sbase);
        ulonglong2 a23 = *reinterpret_cast<const ulonglong2*>(sbase + OFF23);
        ulonglong2 b01 = *reinterpret_cast<const ulonglong2*>(sbase + OFFB);
        ulonglong2 b23 = *reinterpret_cast<const ulonglong2*>(sbase + OFF23 + OFFB);
        sbase += 512;

        #pragma unroll
        for (int v = 0; v < 4; v++) {
            #pragma unroll
            for (int bi = 0; bi < 2; bi++) {
                const ulonglong2& x01 = bi ? b01 : a01;
                const ulonglong2& x23 = bi ? b23 : a23;
                int o = v * 2 + bi;
                u64 acc = fma2(x01.x, G[v][0], add2(x23.y, LW[v]));
                acc = fma2(x01.y, G[v][1], acc);
                acc = fma2(x23.x, G[v][2], acc);
                float alo, ahi; upk2(acc, alo, ahi);
                // top-2 on exponent (ALU pipe, overlaps MUFU below)
                m1[o] = fmaxf(m1[o], fminf(m0[o], alo));
                m0[o] = fmaxf(m0[o], alo);
                m1[o] = fmaxf(m1[o], fminf(m0[o], ahi));
                m0[o] = fmaxf(m0[o], ahi);
                u64 vv = pk2(ex2f(alo), ex2f(ahi));      // v in [0,1]
                u64 q = fma2(Cq3, vv, Cq2);
                q = fma2(q, vv, Cq1);
                q = fma2(q, vv, Cq0);
                S[o] = fma2(q, vv, S[o]);
            }
        }
    }

    // cross-lane reduction per output (butterfly top-2 on exponents + sum)
    float res = 0.f;
    #pragma unroll
    for (int o = 0; o < 8; o++) {
        float slo, shi; upk2(S[o], slo, shi);
        float Sf = slo + shi;
        float M0 = m0[o], M1 = m1[o];
        #pragma unroll
        for (int off = 16; off; off >>= 1) {
            float o0 = __shfl_xor_sync(0xffffffffu, M0, off);
            float o1 = __shfl_xor_sync(0xffffffffu, M1, off);
            float os = __shfl_xor_sync(0xffffffffu, Sf, off);
            M1 = fmaxf(fmaxf(M1, o1), fminf(M0, o0));
            M0 = fmaxf(M0, o0);
            Sf += os;
        }
        if (lane == o) {
            float v0 = exp2f(M0), v1 = exp2f(M1);
            res = (__expf(v0) - __expf(v1)) / (Sf + 1024.0f * C0F);
        }
    }
    if (lane < 8) {
        int v = lane >> 1, bi = lane & 1;
        out[(2 * bh + bi) * VOXN + vox0 + v] = res;
    }
}

extern "C" void kernel_launch(void* const* d_in, const int* in_sizes, int n_in,
                              void* d_out, int out_size) {
    const float* xyz = nullptr; const float* grid = nullptr;
    const float* s1 = nullptr;  const float* s2 = nullptr;
    for (int i = 0; i < n_in; i++) {
        if (in_sizes[i] == 4 * 3 * NN)      xyz = (const float*)d_in[i];
        else if (in_sizes[i] == 3 * VOXN)   grid = (const float*)d_in[i];
        else if (in_sizes[i] == 1) { if (!s1) s1 = (const float*)d_in[i]; else s2 = (const float*)d_in[i]; }
    }
    float* out = (float*)d_out;

    pv_prep<<<144, 256>>>(xyz, grid, s1, s2);
    // 131072 outputs, 8 per warp, 8 warps/block -> 2048 blocks of 256 threads
    pv_main<<<2048, 256>>>(out);
}

// round 8
// speedup vs baseline: 1.1150x; 1.1150x over previous
#include <cuda_runtime.h>
#include <math.h>

// P2V: out[b,vox] = top2-margin of softmax_n( |s2| * exp(-|s1| * |xyz[b,:,n]-grid[:,vox]|^2) )
// margin = (exp(v0)-exp(v1)) / sum_n exp(v_n),  v_n in (0,1]
//
// v_n = 2^( kx0*g0 + kx1*g1 + kx2*g2 + p_n + lw_vox )   (one MUFU ex2 per n)
//   per-(b,n) table g_tab2[b][pair] = {kx0 pair, kx1 pair, kx2 pair, p pair} (32B rows)
//   lw = log2|s2| - s1*log2e*|g|^2  (per-voxel table {g0,g1,g2,lw})
// Sum of exp(v): deg-4 minimax poly, S=fma2(Q,v,S), +1024*c0 once.
// Top-2 tracked on the exponent acc (monotone) via scalar FMNMX (ALU pipe).
// Block epilogue: partials -> padded smem, one warp reduces all 32 outputs
// (replaces 4x8 five-stage shuffle butterflies).

typedef unsigned long long u64;

#define VOXN 32768
#define NN   1024

// [b][pair][ kx0_n, kx0_n1, kx1_n, kx1_n1, kx2_n, kx2_n1, p_n, p_n1 ]
__device__ __align__(256) float  g_tab2[4][512][8];
__device__ __align__(16)  float4 g_vox[VOXN];

__device__ __forceinline__ u64 pk2(float lo, float hi) {
    u64 r; asm("mov.b64 %0, {%1, %2};" : "=l"(r) : "f"(lo), "f"(hi)); return r;
}
__device__ __forceinline__ void upk2(u64 v, float& lo, float& hi) {
    asm("mov.b64 {%0, %1}, %2;" : "=f"(lo), "=f"(hi) : "l"(v));
}
__device__ __forceinline__ u64 fma2(u64 a, u64 b, u64 c) {
    u64 d; asm("fma.rn.f32x2 %0, %1, %2, %3;" : "=l"(d) : "l"(a), "l"(b), "l"(c)); return d;
}
__device__ __forceinline__ u64 add2(u64 a, u64 b) {
    u64 d; asm("add.rn.f32x2 %0, %1, %2;" : "=l"(d) : "l"(a), "l"(b)); return d;
}
__device__ __forceinline__ float ex2f(float x) {
    float r; asm("ex2.approx.ftz.f32 %0, %1;" : "=f"(r) : "f"(x)); return r;
}

// deg-4 minimax for e^x on [0,1], |err| ~ 3e-5
#define C4F 0.0695600f
#define C3F 0.1400096f
#define C2F 0.5099252f
#define C1F 0.9987378f
#define C0F 1.0000236f

// ---- fused prologue: blocks 0-127 per-voxel, blocks 128-143 per-(b,n) tables ----
__global__ void pv_prep(const float* __restrict__ xyz,
                        const float* __restrict__ grid,
                        const float* __restrict__ s1,
                        const float* __restrict__ s2) {
    const float L = 1.4426950408889634f;
    float s1a = fabsf(s1[0]);
    if (blockIdx.x < 128) {
        int vx = blockIdx.x * 256 + threadIdx.x;
        float g0 = grid[vx];
        float g1 = grid[VOXN + vx];
        float g2 = grid[2 * VOXN + vx];
        float lw = __log2f(fabsf(s2[0])) - s1a * L * (g0 * g0 + g1 * g1 + g2 * g2);
        g_vox[vx] = make_float4(g0, g1, g2, lw);
    } else {
        int i = (blockIdx.x - 128) * 256 + threadIdx.x;   // 0..4095
        if (i >= 4 * NN) return;
        int b = i >> 10, n = i & (NN - 1);
        float k = 2.0f * s1a * L;
        float x0 = xyz[b * 3 * NN + 0 * NN + n];
        float x1 = xyz[b * 3 * NN + 1 * NN + n];
        float x2 = xyz[b * 3 * NN + 2 * NN + n];
        int pr = n >> 1, h = n & 1;
        g_tab2[b][pr][0 + h] = k * x0;
        g_tab2[b][pr][2 + h] = k * x1;
        g_tab2[b][pr][4 + h] = k * x2;
        g_tab2[b][pr][6 + h] = -s1a * L * (x0 * x0 + x1 * x1 + x2 * x2);
    }
}

// ---- main: one warp -> 4 voxels x 2 batches = 8 outputs; block = 4 warps ----
__global__ void __launch_bounds__(128, 6) pv_main(float* __restrict__ out)
{
    __shared__ float sm0[32][33];
    __shared__ float sm1[32][33];
    __shared__ float sS[32][33];

    int tid  = threadIdx.x;
    int lane = tid & 31;
    int wig  = tid >> 5;                     // 0..3
    int warp = blockIdx.x * 4 + wig;
    int vg   = warp >> 1;                    // voxel group (4 voxels)
    int bh   = warp & 1;                     // batches {2bh, 2bh+1}
    int vox0 = vg * 4;

    // per-voxel broadcast constants
    u64 G[4][3], LW[4];
    #pragma unroll
    for (int v = 0; v < 4; v++) {
        float4 gv = g_vox[vox0 + v];
        G[v][0] = pk2(gv.x, gv.x);
        G[v][1] = pk2(gv.y, gv.y);
        G[v][2] = pk2(gv.z, gv.z);
        LW[v]   = pk2(gv.w, gv.w);
    }

    const u64 Cq3 = pk2(C4F, C4F);
    const u64 Cq2 = pk2(C3F, C3F);
    const u64 Cq1 = pk2(C2F, C2F);
    const u64 Cq0 = pk2(C1F, C1F);

    u64 S[8];
    float m0[8], m1[8];
    #pragma unroll
    for (int o = 0; o < 8; o++) { S[o] = 0ull; m0[o] = -1e30f; m1[o] = -1e30f; }

    // table pointer: u64 units. per-b stride = 512 pairs * 4 u64 = 2048.
    const u64* tp = reinterpret_cast<const u64*>(g_tab2) + (u64)(2 * bh) * 2048 + lane * 4;

    #pragma unroll 2
    for (int j = 0; j < 16; j++) {
        ulonglong2 a0 = reinterpret_cast<const ulonglong2*>(tp)[0];        // {kx0, kx1}
        ulonglong2 a1 = reinterpret_cast<const ulonglong2*>(tp)[1];        // {kx2, p}
        ulonglong2 b0 = reinterpret_cast<const ulonglong2*>(tp + 2048)[0];
        ulonglong2 b1 = reinterpret_cast<const ulonglong2*>(tp + 2048)[1];
        u64 X[2][4] = { { a0.x, a0.y, a1.x, a1.y }, { b0.x, b0.y, b1.x, b1.y } };

        #pragma unroll
        for (int v = 0; v < 4; v++) {
            #pragma unroll
            for (int bi = 0; bi < 2; bi++) {
                int o = v * 2 + bi;
                u64 acc = fma2(X[bi][0], G[v][0], add2(X[bi][3], LW[v]));
                acc = fma2(X[bi][1], G[v][1], acc);
                acc = fma2(X[bi][2], G[v][2], acc);
                float alo, ahi; upk2(acc, alo, ahi);
                // issue MUFU early...
                u64 vv = pk2(ex2f(alo), ex2f(ahi));      // v in [0,1]
                // ...top-2 on exponent (ALU pipe) fills the MUFU shadow
                m1[o] = fmaxf(m1[o], fminf(m0[o], alo));
                m0[o] = fmaxf(m0[o], alo);
                m1[o] = fmaxf(m1[o], fminf(m0[o], ahi));
                m0[o] = fmaxf(m0[o], ahi);
                u64 q = fma2(Cq3, vv, Cq2);
                q = fma2(q, vv, Cq1);
                q = fma2(q, vv, Cq0);
                S[o] = fma2(q, vv, S[o]);
            }
        }
        tp += 128;
    }

    // dump per-lane partials to smem (one row per output, padded stride 33)
    #pragma unroll
    for (int o = 0; o < 8; o++) {
        float slo, shi; upk2(S[o], slo, shi);
        int outid = wig * 8 + o;
        sm0[outid][lane] = m0[o];
        sm1[outid][lane] = m1[o];
        sS[outid][lane]  = slo + shi;
    }
    __syncthreads();

    // one warp reduces all 32 outputs of the block
    if (tid < 32) {
        int t = tid;                         // output id within block
        float M0 = -1e30f, M1 = -1e30f, Sf = 0.f;
        #pragma unroll
        for (int l = 0; l < 32; l++) {
            float a = sm0[t][l];
            float b = sm1[t][l];
            M1 = fmaxf(fmaxf(M1, b), fminf(M0, a));
            M0 = fmaxf(M0, a);
            Sf += sS[t][l];
        }
        float v0 = exp2f(M0), v1 = exp2f(M1);
        float res = (__expf(v0) - __expf(v1)) / (Sf + 1024.0f * C0F);

        int w  = t >> 3;                     // warp in block
        int o  = t & 7;
        int wr = blockIdx.x * 4 + w;
        int vgr = wr >> 1, bhr = wr & 1;
        int v  = o >> 1, bi = o & 1;
        out[(2 * bhr + bi) * VOXN + vgr * 4 + v] = res;
    }
}

extern "C" void kernel_launch(void* const* d_in, const int* in_sizes, int n_in,
                              void* d_out, int out_size) {
    const float* xyz = nullptr; const float* grid = nullptr;
    const float* s1 = nullptr;  const float* s2 = nullptr;
    for (int i = 0; i < n_in; i++) {
        if (in_sizes[i] == 4 * 3 * NN)      xyz = (const float*)d_in[i];
        else if (in_sizes[i] == 3 * VOXN)   grid = (const float*)d_in[i];
        else if (in_sizes[i] == 1) { if (!s1) s1 = (const float*)d_in[i]; else s2 = (const float*)d_in[i]; }
    }
    float* out = (float*)d_out;

    pv_prep<<<144, 256>>>(xyz, grid, s1, s2);
    // 131072 outputs, 8 per warp -> 16384 warps -> 4096 blocks of 4 warps
    pv_main<<<4096, 128>>>(out);
}